// round 3
// baseline (speedup 1.0000x reference)
#include <cuda_runtime.h>
#include <cuda_bf16.h>
#include <math.h>

// Cox partial-likelihood loss, N=8192, CENSORING < 0 (gate == event).
//
// O(N) reformulation via counting sort on ytime buckets:
//   S_m = sum_k [ytime_k >= ytime_m] * exp(pred_k)
//       = (sum over buckets strictly above b_m) + (bucket-mates with yt_j >= yt_m)
//   loss = sum_m event_m * (log(S_m) - pred_m) / sum_m event_m
//
// All accumulation in u64 fixed point (scale 2^43) -> atomicAdd is associative
// -> results are bitwise deterministic despite nondeterministic atomic order.

#define CN    8192
#define B     4096               // buckets; ytime in [0,10) -> avg occupancy 2
#define BSCALE 409.6f            // B / 10.0
#define FXSCALE 8796093022208.0  // 2^43
#define INV_FX (1.0 / 8796093022208.0)
#define FBLK  8

__device__ unsigned int       g_cnt[B];        // zeroed at end of each call
__device__ unsigned long long g_bsum[B];       // zeroed at end of each call
__device__ unsigned int       g_off[B + 1];
__device__ unsigned int       g_cur[B];
__device__ unsigned long long g_pfx[B];        // inclusive prefix of g_bsum
__device__ unsigned long long g_ef[CN];        // exp(pred) fixed-point, per element
__device__ int                g_bk[CN];        // bucket per element
__device__ float              g_syt[CN];       // scattered ytime (bucket-sorted)
__device__ unsigned long long g_sef[CN];       // scattered e fixed-point
__device__ float              g_red[FBLK][2];

__device__ __forceinline__ int bucket_of(float yt) {
    int b = (int)(yt * BSCALE);
    return b > (B - 1) ? (B - 1) : b;
}

// ---------------- K1: per-element exp + bucket histogram ----------------
__global__ __launch_bounds__(256) void bucket_kernel(
    const float* __restrict__ pred,
    const float* __restrict__ ytime)
{
    const int k = blockIdx.x * 256 + threadIdx.x;
    const float yt = ytime[k];
    const float e  = expf(pred[k]);
    const int b = bucket_of(yt);
    const unsigned long long ef = (unsigned long long)((double)e * FXSCALE);
    g_ef[k] = ef;
    g_bk[k] = b;
    atomicAdd(&g_cnt[b], 1u);
    atomicAdd(&g_bsum[b], ef);
}

// ---------------- K2: prefix scans over buckets (single block) ----------------
__global__ __launch_bounds__(1024) void scan_kernel()
{
    __shared__ unsigned int       s_wc[32];
    __shared__ unsigned long long s_wb[32];
    const int t = threadIdx.x;
    const int lane = t & 31, wid = t >> 5;
    const int i0 = t * 4;

    unsigned int c[4];
    unsigned long long bs[4];
    #pragma unroll
    for (int i = 0; i < 4; ++i) { c[i] = g_cnt[i0 + i]; bs[i] = g_bsum[i0 + i]; }
    const unsigned int csum = c[0] + c[1] + c[2] + c[3];
    const unsigned long long bsm = bs[0] + bs[1] + bs[2] + bs[3];

    // inclusive warp scan of per-thread sums
    unsigned int ci = csum;
    unsigned long long bi = bsm;
    #pragma unroll
    for (int o = 1; o < 32; o <<= 1) {
        unsigned int       cn = __shfl_up_sync(0xFFFFFFFFu, ci, o);
        unsigned long long bn = __shfl_up_sync(0xFFFFFFFFu, bi, o);
        if (lane >= o) { ci += cn; bi += bn; }
    }
    if (lane == 31) { s_wc[wid] = ci; s_wb[wid] = bi; }
    __syncthreads();
    if (wid == 0) {
        const unsigned int       wc = s_wc[lane];
        const unsigned long long wb = s_wb[lane];
        unsigned int wci = wc;
        unsigned long long wbi = wb;
        #pragma unroll
        for (int o = 1; o < 32; o <<= 1) {
            unsigned int       cn = __shfl_up_sync(0xFFFFFFFFu, wci, o);
            unsigned long long bn = __shfl_up_sync(0xFFFFFFFFu, wbi, o);
            if (lane >= o) { wci += cn; wbi += bn; }
        }
        s_wc[lane] = wci - wc;   // exclusive base per warp
        s_wb[lane] = wbi - wb;
    }
    __syncthreads();

    unsigned int       off = s_wc[wid] + (ci - csum);  // global exclusive base
    unsigned long long bp  = s_wb[wid] + (bi - bsm);
    #pragma unroll
    for (int i = 0; i < 4; ++i) {
        g_off[i0 + i] = off;
        g_cur[i0 + i] = off;
        off += c[i];
        bp  += bs[i];
        g_pfx[i0 + i] = bp;      // inclusive prefix
    }
    if (t == 1023) g_off[B] = off;
}

// ---------------- K3: counting-sort scatter ----------------
__global__ __launch_bounds__(256) void scatter_kernel(
    const float* __restrict__ ytime)
{
    const int k = blockIdx.x * 256 + threadIdx.x;
    const int b = g_bk[k];
    const unsigned int pos = atomicAdd(&g_cur[b], 1u);
    g_syt[pos] = ytime[k];
    g_sef[pos] = g_ef[k];
}

// ---------------- K4: per-m loss term + block reduce ----------------
__global__ __launch_bounds__(1024) void per_m_kernel(
    const float* __restrict__ pred,
    const float* __restrict__ ytime,
    const int*   __restrict__ event)
{
    __shared__ float red_a[32];
    __shared__ float red_b[32];

    const int m = blockIdx.x * 1024 + threadIdx.x;
    const float yt = ytime[m];
    const int b = bucket_of(yt);

    // sum over all buckets strictly above b (exact integer arithmetic)
    unsigned long long S = g_pfx[B - 1] - g_pfx[b];
    // bucket-mates with yt_j >= yt (includes m itself); order-invariant u64 sum
    const unsigned int lo = g_off[b], hi = g_off[b + 1];
    for (unsigned int j = lo; j < hi; ++j)
        if (g_syt[j] >= yt) S += g_sef[j];

    const float Sf = (float)((double)S * INV_FX);
    const float ev = (float)event[m];
    float a = ev * (logf(Sf) - pred[m]);
    float w = ev;

    #pragma unroll
    for (int o = 16; o > 0; o >>= 1) {
        a += __shfl_xor_sync(0xFFFFFFFFu, a, o);
        w += __shfl_xor_sync(0xFFFFFFFFu, w, o);
    }
    const int lane = threadIdx.x & 31;
    const int wid  = threadIdx.x >> 5;
    if (lane == 0) { red_a[wid] = a; red_b[wid] = w; }
    __syncthreads();
    if (wid == 0) {
        a = red_a[lane];
        w = red_b[lane];
        #pragma unroll
        for (int o = 16; o > 0; o >>= 1) {
            a += __shfl_xor_sync(0xFFFFFFFFu, a, o);
            w += __shfl_xor_sync(0xFFFFFFFFu, w, o);
        }
        if (lane == 0) { g_red[blockIdx.x][0] = a; g_red[blockIdx.x][1] = w; }
    }
}

// ---------------- K5: scalar combine + re-zero counters for replay ----------------
__global__ __launch_bounds__(256) void final_kernel(float* __restrict__ out)
{
    const int idx = blockIdx.x * 256 + threadIdx.x;   // 32 blocks * 256 = 8192
    if (idx < B) { g_cnt[idx] = 0u; g_bsum[idx] = 0ull; }
    if (idx == 0) {
        float a = 0.f, w = 0.f;
        #pragma unroll
        for (int i = 0; i < FBLK; ++i) { a += g_red[i][0]; w += g_red[i][1]; }
        out[0] = a / w;
    }
}

extern "C" void kernel_launch(void* const* d_in, const int* in_sizes, int n_in,
                              void* d_out, int out_size)
{
    const float* pred  = (const float*)d_in[0];
    const float* ytime = (const float*)d_in[1];
    const int*   event = (const int*)d_in[2];
    float*       out   = (float*)d_out;

    bucket_kernel<<<CN / 256, 256>>>(pred, ytime);
    scan_kernel<<<1, 1024>>>();
    scatter_kernel<<<CN / 256, 256>>>(ytime);
    per_m_kernel<<<FBLK, 1024>>>(pred, ytime, event);
    final_kernel<<<CN / 256, 256>>>(out);
}